// round 9
// baseline (speedup 1.0000x reference)
#include <cuda_runtime.h>
#include <cstdint>

// Problem constants: coords in [0,256)^3, R=2 -> coarse coords in [0,128)^3.
// Coarse key = (bx<<14)|(by<<7)|bz (21 bits). Ascending key order ==
// lexicographic row order == jnp.unique's sorted output (verified rel_err=0.0).
static constexpr int NKEYS  = 1 << 21;        // 2,097,152 coarse cells
static constexpr int NWORDS = NKEYS / 32;     // 65,536 bitmask words (256 KB)
static constexpr int MAXN   = 524288;         // >= 500,000 points

// Scratch (static __device__ globals — no allocation allowed)
__device__ unsigned int g_bits[NWORDS];       // 256 KB: presence bitmask (L2-resident)
__device__ unsigned int g_wsum[NWORDS];       // 256 KB: exclusive prefix of popcounts
__device__ int          g_winner[MAXN * 8];   // 16 MB: last-writer idx+1 per slot

// ---------------------------------------------------------------------------
// Clear bits + winner; pre-fill out_coords with -1.0f (jnp.unique fill value,
// emitted as float32 — the harness output buffer dtype is float32).
__global__ void k_init(long long w4, float* __restrict__ out_coords, int n3) {
    long long i = (long long)blockIdx.x * blockDim.x + threadIdx.x;
    long long stride = (long long)gridDim.x * blockDim.x;
    uint4 z = make_uint4(0u, 0u, 0u, 0u);
    const long long b4 = NWORDS / 4;
    for (long long j = i; j < b4; j += stride)
        reinterpret_cast<uint4*>(g_bits)[j] = z;
    for (long long j = i; j < w4; j += stride)
        reinterpret_cast<uint4*>(g_winner)[j] = z;
    for (long long j = i; j < n3; j += stride)
        out_coords[j] = -1.0f;
}

// ---------------------------------------------------------------------------
// Mark present coarse keys in the bitmask
__global__ void k_mark(const int* __restrict__ coords, int n) {
    int i = blockIdx.x * blockDim.x + threadIdx.x;
    if (i >= n) return;
    int cx = coords[3 * i], cy = coords[3 * i + 1], cz = coords[3 * i + 2];
    unsigned key = ((unsigned)(cx >> 1) << 14) | ((unsigned)(cy >> 1) << 7)
                 | (unsigned)(cz >> 1);
    atomicOr(&g_bits[key >> 5], 1u << (key & 31));
}

// ---------------------------------------------------------------------------
// Single-block exclusive scan of per-word popcounts over all 65536 words.
// Two L2-resident passes (reads 2x256KB) + one shared-memory block scan.
static constexpr int SCAN_T  = 1024;
static constexpr int WPT     = NWORDS / SCAN_T;   // 64 words per thread
__global__ void k_scan() {
    __shared__ unsigned sh[SCAN_T];
    int t = threadIdx.x;
    int base = t * WPT;
    // pass 1: per-thread popcount total
    unsigned s = 0;
#pragma unroll 4
    for (int k = 0; k < WPT / 4; k++) {
        uint4 a = *reinterpret_cast<const uint4*>(g_bits + base + k * 4);
        s += __popc(a.x) + __popc(a.y) + __popc(a.z) + __popc(a.w);
    }
    sh[t] = s;
    __syncthreads();
    // Hillis-Steele inclusive scan over 1024 thread totals
    for (int off = 1; off < SCAN_T; off <<= 1) {
        unsigned x = (t >= off) ? sh[t - off] : 0u;
        __syncthreads();
        sh[t] += x;
        __syncthreads();
    }
    unsigned run = sh[t] - s;   // exclusive offset for this thread
    // pass 2: write exclusive word prefixes
#pragma unroll 4
    for (int k = 0; k < WPT / 4; k++) {
        uint4 a = *reinterpret_cast<const uint4*>(g_bits + base + k * 4);
        uint4 o;
        o.x = run; run += __popc(a.x);
        o.y = run; run += __popc(a.y);
        o.z = run; run += __popc(a.z);
        o.w = run; run += __popc(a.w);
        *reinterpret_cast<uint4*>(g_wsum + base + k * 4) = o;
    }
}

// ---------------------------------------------------------------------------
// Fused: emit sorted unique coords (threads < NWORDS, one word each) AND
// record the last-wins winner per (row, slot) (threads < n, one point each).
// atomicMax(i+1) == "last index wins", matching XLA's sequential scatter.
__global__ void k_post(const int* __restrict__ coords, int n,
                       float* __restrict__ out_coords) {
    int gid = blockIdx.x * blockDim.x + threadIdx.x;

    if (gid < NWORDS) {
        unsigned m = g_bits[gid];
        if (m) {
            unsigned r = g_wsum[gid];
            unsigned wbase = (unsigned)gid << 5;
            while (m) {
                int b = __ffs(m) - 1;
                m &= m - 1;
                unsigned key = wbase + b;
                out_coords[3 * r]     = (float)(key >> 14);
                out_coords[3 * r + 1] = (float)((key >> 7) & 127);
                out_coords[3 * r + 2] = (float)(key & 127);
                r++;
            }
        }
    }

    if (gid < n) {
        int cx = coords[3 * gid], cy = coords[3 * gid + 1], cz = coords[3 * gid + 2];
        unsigned key = ((unsigned)(cx >> 1) << 14) | ((unsigned)(cy >> 1) << 7)
                     | (unsigned)(cz >> 1);
        unsigned w   = key >> 5;
        unsigned inv = g_wsum[w] + __popc(g_bits[w] & ((1u << (key & 31)) - 1u));
        unsigned off = ((unsigned)(cx & 1) << 2) | ((unsigned)(cy & 1) << 1)
                     | (unsigned)(cz & 1);
        atomicMax(&g_winner[inv * 8 + off], gid + 1);
    }
}

// ---------------------------------------------------------------------------
// Gather epilogue: one thread per (row, slot); writes agg exactly once.
// Empty slots -> zeros; occupied -> 16 channels of the winning point.
__global__ void k_gather(const float* __restrict__ feats,
                         float* __restrict__ agg, long long nslots) {
    long long s = (long long)blockIdx.x * blockDim.x + threadIdx.x;
    if (s >= nslots) return;
    int w = g_winner[s];
    float4* dst = reinterpret_cast<float4*>(agg + s * 16);
    if (w == 0) {
        float4 z = make_float4(0.f, 0.f, 0.f, 0.f);
        dst[0] = z; dst[1] = z; dst[2] = z; dst[3] = z;
    } else {
        const float4* src = reinterpret_cast<const float4*>(feats + (size_t)(w - 1) * 16);
        dst[0] = src[0];
        dst[1] = src[1];
        dst[2] = src[2];
        dst[3] = src[3];
    }
}

// ---------------------------------------------------------------------------
extern "C" void kernel_launch(void* const* d_in, const int* in_sizes, int n_in,
                              void* d_out, int out_size) {
    const float* feats  = (const float*)d_in[0];   // [n,16] f32
    const int*   coords = (const int*)d_in[1];     // [n,3]  i32
    const int n = in_sizes[0] / 16;

    // Output layout (all float32): unique_coords [n,3] then agg [n,128]
    float* out_coords = (float*)d_out;
    float* agg        = (float*)d_out + (size_t)n * 3;

    const int TB = 256;
    const int nb_pts = (n + TB - 1) / TB;

    // 1) clear bitmask + winner, fill coords section with -1.0f
    long long w4 = (long long)n * 2;               // n*8 ints / 4
    k_init<<<2048, TB>>>(w4, out_coords, n * 3);

    // 2) mark presence bits
    k_mark<<<nb_pts, TB>>>(coords, n);

    // 3) single-kernel exclusive popcount scan (L2-resident, 256 KB)
    k_scan<<<1, SCAN_T>>>();

    // 4) fused emit(sorted unique coords) + winner(last-wins per slot)
    int nb_post = (n > NWORDS ? nb_pts : (NWORDS + TB - 1) / TB);
    k_post<<<nb_post, TB>>>(coords, n, out_coords);

    // 5) single-write gather epilogue
    long long nslots = (long long)n * 8;
    int nb_slots = (int)((nslots + TB - 1) / TB);
    k_gather<<<nb_slots, TB>>>(feats, agg, nslots);
}